// round 8
// baseline (speedup 1.0000x reference)
#include <cuda_runtime.h>
#include <cuda_bf16.h>
#include <math.h>

// Fixed shapes: cls_conv_out (4, 1029, 100, 100) fp32; rois (2000,4) int32.
// Only batch 3 used. Output (2000, 21, 1, 1) fp32.
#define KK       7
#define C1       21
#define NJL      49
#define H        100
#define W        100
#define HP       101
#define ROW_S    2124                 // HP*C1=2121 padded to mult of 4 (16B-aligned rows)
#define ROW4     (ROW_S / 4)          // 531
#define PLANE_S  (HP * ROW_S)
#define IN_BASE  (3 * 1029 * 10000)   // batch 3 offset
#define NS       10                   // strips over y
#define RPS      10                   // rows per strip

// Strip-LOCAL integrals, rows 1..100 (row 0 unused; y==0 handled in kernel C).
__device__ float g_integral[(size_t)NJL * PLANE_S];
// Per-strip totals and their exclusive prefix (the strip base offsets).
__device__ float g_T  [(size_t)NJL * NS * ROW_S];
__device__ float g_off[(size_t)NJL * NS * ROW_S];

// ---------------------------------------------------------------------------
// Fused x-scan + strip-local y-cumsum. Block = (strip s, jl). For each of 10
// input rows: float4 load, warp shuffle x-scan, smem transpose (double-
// buffered, 1 sync/row), acc (registers, transposed layout) += row, store.
// Strip total T written at the end.
// ---------------------------------------------------------------------------
__global__ void __launch_bounds__(128) fused_scan(const float* __restrict__ in) {
    const int s    = blockIdx.x;       // 0..9
    const int jl   = blockIdx.y;       // 0..48
    const int t    = threadIdx.x;
    const int w    = t >> 5, lane = t & 31;

    __shared__ float sm[2][C1 * HP];   // sm[buf][c*101 + x], inclusive x-cumsum

    // Transposed-slot ownership: thread owns float4 slots i4 = t + 128*q.
    // Precompute (x, c) of element e = 4*i4 once.
    int xq[5], cq[5];
    #pragma unroll
    for (int q = 0; q < 5; q++) {
        const int e = 4 * (t + 128 * q);
        xq[q] = e / C1;
        cq[q] = e - xq[q] * C1;
    }
    float4 acc[5];
    #pragma unroll
    for (int q = 0; q < 5; q++) acc[q] = make_float4(0.f, 0.f, 0.f, 0.f);

    const float4* base4 = (const float4*)(in + IN_BASE + (size_t)jl * (C1 * H * W));
    float* outplane = g_integral + (size_t)jl * PLANE_S;

    for (int i = 0; i < RPS; i++) {
        const int r = s * RPS + i;         // input row index (0..99)
        float* buf = sm[i & 1];

        // load + x-scan: warp w owns channels {w, w+4, ...}; lanes 0..24
        #pragma unroll
        for (int k = 0; k < 6; k++) {
            const int c = w + 4 * k;
            if (c < C1) {
                float4 vv;
                if (lane < 25) vv = base4[c * (H * W / 4) + r * (W / 4) + lane];
                float s0 = vv.x;
                float s1 = s0 + vv.y;
                float s2 = s1 + vv.z;
                float s3 = s2 + vv.w;
                float run = s3;
                #pragma unroll
                for (int d = 1; d < 32; d <<= 1) {
                    float u = __shfl_up_sync(0xffffffffu, run, d);
                    if (lane >= d) run += u;
                }
                const float off = run - s3;
                if (lane < 25) {
                    float* dst = buf + c * HP + 4 * lane;
                    dst[0] = off + s0; dst[1] = off + s1;
                    dst[2] = off + s2; dst[3] = off + s3;
                }
            }
        }
        __syncthreads();

        // transposed gather + accumulate + store local integral row r+1
        float* outrow = outplane + (size_t)(r + 1) * ROW_S;
        #pragma unroll
        for (int q = 0; q < 5; q++) {
            const int i4 = t + 128 * q;
            if (i4 < ROW4) {
                int xx = xq[q], cc = cq[q];
                float4 f;
                #define GETF(FIELD)                                              \
                    f.FIELD = ((unsigned)(xx - 1) < 100u)                        \
                                  ? buf[cc * HP + xx - 1] : 0.0f;                \
                    if (++cc == C1) { cc = 0; ++xx; }
                GETF(x) GETF(y) GETF(z) GETF(w)
                #undef GETF
                acc[q].x += f.x; acc[q].y += f.y;
                acc[q].z += f.z; acc[q].w += f.w;
                ((float4*)outrow)[i4] = acc[q];
            }
        }
    }

    // strip total
    float* Trow = g_T + ((size_t)jl * NS + s) * ROW_S;
    #pragma unroll
    for (int q = 0; q < 5; q++) {
        const int i4 = t + 128 * q;
        if (i4 < ROW4) ((float4*)Trow)[i4] = acc[q];
    }
}

// ---------------------------------------------------------------------------
// Fixup: exclusive prefix of strip totals -> per-strip base offsets.
// ---------------------------------------------------------------------------
__global__ void fixup() {
    const int jl    = blockIdx.y;
    const int slot4 = blockIdx.x * blockDim.x + threadIdx.x;
    if (slot4 >= ROW4) return;

    const float4* T = (const float4*)(g_T   + (size_t)jl * NS * ROW_S) + slot4;
    float4*       O = (float4*)      (g_off + (size_t)jl * NS * ROW_S) + slot4;

    float4 run = make_float4(0.f, 0.f, 0.f, 0.f);
    #pragma unroll
    for (int s = 0; s < NS; s++) {
        O[(size_t)s * ROW4] = run;
        float4 v = T[(size_t)s * ROW4];
        run.x += v.x; run.y += v.y; run.z += v.z; run.w += v.w;
    }
}

// ---------------------------------------------------------------------------
// Kernel C: one block per ROI. Corner value = local[y] + off[(y-1)/10]
// (0 if y==0). Deterministic reduction + warp softmax.
// ---------------------------------------------------------------------------
__global__ void pool_softmax(const int* __restrict__ rois,
                             float* __restrict__ out) {
    const int roi = blockIdx.x;
    const int t   = threadIdx.x;
    __shared__ float s_S[NJL * C1];
    __shared__ float s_avg[C1];

    const int4 r = ((const int4*)rois)[roi];   // ymin, xmin, ymax, xmax
    const int ys = (r.z - r.x) / KK;
    const int xs = (r.w - r.y) / KK;

    if (t < 336) {
        const int c   = t % C1;
        const int jl0 = t / C1;   // 0..15
        #pragma unroll
        for (int jl = jl0; jl < NJL; jl += 16) {
            const int j = jl / KK, l = jl - j * KK;
            const int y0 = r.x + j * ys, y1 = y0 + ys;
            const int x0 = r.y + l * xs, x1 = x0 + xs;
            const float* P = g_integral + (size_t)jl * PLANE_S;
            const float* O = g_off + (size_t)jl * NS * ROW_S;
            const int st1 = (y1 - 1) / NS;
            const float a = P[(size_t)y1 * ROW_S + x1 * C1 + c]
                          + O[(size_t)st1 * ROW_S + x1 * C1 + c];
            const float d = P[(size_t)y1 * ROW_S + x0 * C1 + c]
                          + O[(size_t)st1 * ROW_S + x0 * C1 + c];
            float b = 0.f, e = 0.f;
            if (y0 > 0) {
                const int st0 = (y0 - 1) / NS;
                b = P[(size_t)y0 * ROW_S + x1 * C1 + c]
                  + O[(size_t)st0 * ROW_S + x1 * C1 + c];
                e = P[(size_t)y0 * ROW_S + x0 * C1 + c]
                  + O[(size_t)st0 * ROW_S + x0 * C1 + c];
            }
            s_S[jl * C1 + c] = (a - b) - (d - e);
        }
    }
    __syncthreads();

    if (t < C1) {
        float acc = 0.0f;
        #pragma unroll 7
        for (int jl = 0; jl < NJL; jl++) acc += s_S[jl * C1 + t];
        s_avg[t] = acc / (49.0f * (float)(ys * xs));
    }
    __syncthreads();

    if (t < 32) {
        const bool act = t < C1;
        float v = act ? s_avg[t] : -INFINITY;
        float m = v;
        #pragma unroll
        for (int o = 16; o; o >>= 1) m = fmaxf(m, __shfl_xor_sync(0xffffffffu, m, o));
        float e = act ? expf(v - m) : 0.0f;
        float sum = e;
        #pragma unroll
        for (int o = 16; o; o >>= 1) sum += __shfl_xor_sync(0xffffffffu, sum, o);
        if (act) out[(size_t)roi * C1 + t] = e / sum;
    }
}

// ---------------------------------------------------------------------------
extern "C" void kernel_launch(void* const* d_in, const int* in_sizes, int n_in,
                              void* d_out, int out_size) {
    const float* x    = (const float*)d_in[0];
    const int*   rois = (const int*)d_in[1];
    float*       out  = (float*)d_out;
    const int n_rois  = in_sizes[1] / 4;   // 2000

    dim3 gF(NS, NJL);                      // 10 x 49 = 490 blocks
    fused_scan<<<gF, 128>>>(x);

    dim3 gX((ROW4 + 127) / 128, NJL);      // 5 x 49
    fixup<<<gX, 128>>>();

    pool_softmax<<<n_rois, 352>>>(rois, out);
}

// round 9
// speedup vs baseline: 1.5923x; 1.5923x over previous
#include <cuda_runtime.h>
#include <cuda_bf16.h>
#include <math.h>

// Fixed shapes: cls_conv_out (4, 1029, 100, 100) fp32; rois (2000,4) int32.
// Only batch 3 used. Output (2000, 21, 1, 1) fp32.
#define KK       7
#define C1       21
#define NJL      49
#define H        100
#define W        100
#define HP       101
#define ROW_S    2124                 // HP*C1=2121 padded to mult of 4 (16B-aligned rows)
#define PLANE_S  (HP * ROW_S)
#define IN_BASE  (3 * 1029 * 10000)   // batch 3 offset

// Integral image, transposed c-innermost: I[jl][y][x][c]; ~42 MB scratch.
__device__ float g_integral[(size_t)NJL * PLANE_S];

// ---------------------------------------------------------------------------
// Kernel A: per (jl, y): float4 global load -> register shuffle-scan x-cumsum
// -> smem stage -> fully-unrolled constant-stride transposed store.
// out offset for thread t (=x0*21+c) at step k is exactly t + 126*k, and the
// smem offset is (x0-1) + 6*k: pure LDS/STG pairs with immediate offsets.
// ---------------------------------------------------------------------------
__global__ void __launch_bounds__(128) build_xsum(const float* __restrict__ in) {
    const int y    = blockIdx.x + 1;   // 1..100
    const int jl   = blockIdx.y;       // 0..48
    const int t    = threadIdx.x;
    const int w    = t >> 5, lane = t & 31;

    __shared__ float sm[C1 * HP];      // sm[c*101 + x] = inclusive cumsum at x

    // --- load: warp w owns channels {w, w+4, ...}; lanes 0..24 hold 1 float4
    const float4* src4 = (const float4*)(in + IN_BASE
                        + (size_t)jl * (C1 * H * W) + (size_t)(y - 1) * W);
    float4 v[6];
    #pragma unroll
    for (int k = 0; k < 6; k++) {
        const int c = w + 4 * k;
        if (c < C1 && lane < 25) v[k] = src4[c * (H * W / 4) + lane];
    }

    // --- scan each owned channel: in-thread scan of 4 + shfl_up over lanes
    #pragma unroll
    for (int k = 0; k < 6; k++) {
        const int c = w + 4 * k;
        if (c < C1) {
            float s0 = v[k].x;
            float s1 = s0 + v[k].y;
            float s2 = s1 + v[k].z;
            float s3 = s2 + v[k].w;
            float run = s3;
            #pragma unroll
            for (int d = 1; d < 32; d <<= 1) {
                float u = __shfl_up_sync(0xffffffffu, run, d);
                if (lane >= d) run += u;
            }
            const float off = run - s3;
            if (lane < 25) {
                float* dst = sm + c * HP + 4 * lane;
                dst[0] = off + s0; dst[1] = off + s1;
                dst[2] = off + s2; dst[3] = off + s3;
            }
        }
    }
    __syncthreads();

    // --- transposed store, fully unrolled, constant strides
    float* outrow = g_integral + ((size_t)jl * HP + y) * ROW_S;
    if (t < 126) {
        const int c  = t % C1;
        const int x0 = t / C1;                   // 0..5
        const float* rs = sm + c * HP + (x0 - 1);
        float* gd = outrow + t;
        gd[0] = (x0 == 0) ? 0.0f : rs[0];        // x = x0 (x==0 only when x0==0)
        #pragma unroll
        for (int k = 1; k < 16; k++) {
            gd[126 * k] = rs[6 * k];             // x = x0 + 6k <= 95+.. always valid
        }
        if (x0 < 5) gd[126 * 16] = rs[6 * 16];   // x = x0+96 valid iff x0<=4
    }
}

// ---------------------------------------------------------------------------
// Kernel B: y-cumsum over float2 slots (1062/row) -> 2x threads vs float4 for
// latency hiding; writes y=0 zero row then 100 dependent FADD2 steps,
// unroll 10 for load MLP.
// ---------------------------------------------------------------------------
__global__ void build_ysum() {
    const int jl    = blockIdx.y;
    const int slot2 = blockIdx.x * blockDim.x + threadIdx.x;
    if (slot2 >= ROW_S / 2) return;

    float2* p = (float2*)(g_integral + (size_t)jl * PLANE_S) + slot2;
    const int stride2 = ROW_S / 2;      // 1062

    float2 acc = make_float2(0.f, 0.f);
    p[0] = acc;                         // y = 0 row is zero
    #pragma unroll 10
    for (int y = 1; y <= H; y++) {
        float2 v = p[(size_t)y * stride2];
        acc.x += v.x; acc.y += v.y;
        p[(size_t)y * stride2] = acc;
    }
}

// ---------------------------------------------------------------------------
// Kernel C: one block per ROI. 336 active threads (16 jl-groups x 21 c);
// per-thread register pre-reduction over its jl values, then 21 threads sum
// 16 partials; warp softmax.
// ---------------------------------------------------------------------------
__global__ void pool_softmax(const int* __restrict__ rois,
                             float* __restrict__ out) {
    const int roi = blockIdx.x;
    const int t   = threadIdx.x;
    __shared__ float s_part[336];      // [jl0*21 + c]
    __shared__ float s_avg[C1];

    const int4 r = ((const int4*)rois)[roi];   // ymin, xmin, ymax, xmax
    const int ys = (r.z - r.x) / KK;
    const int xs = (r.w - r.y) / KK;

    if (t < 336) {
        const int c   = t % C1;
        const int jl0 = t / C1;   // 0..15
        float part = 0.0f;
        #pragma unroll
        for (int jl = jl0; jl < NJL; jl += 16) {
            const int j = jl / KK, l = jl - j * KK;
            const int y0 = r.x + j * ys, y1 = y0 + ys;
            const int x0 = r.y + l * xs, x1 = x0 + xs;
            const float* P = g_integral + (size_t)jl * PLANE_S;
            const float a = P[(size_t)y1 * ROW_S + x1 * C1 + c];
            const float b = P[(size_t)y0 * ROW_S + x1 * C1 + c];
            const float d = P[(size_t)y1 * ROW_S + x0 * C1 + c];
            const float e = P[(size_t)y0 * ROW_S + x0 * C1 + c];
            part += (a - b) - (d - e);
        }
        s_part[t] = part;
    }
    __syncthreads();

    if (t < C1) {
        float acc = 0.0f;
        #pragma unroll
        for (int g = 0; g < 16; g++) acc += s_part[g * C1 + t];
        s_avg[t] = acc / (49.0f * (float)(ys * xs));
    }
    __syncthreads();

    if (t < 32) {
        const bool act = t < C1;
        float v = act ? s_avg[t] : -INFINITY;
        float m = v;
        #pragma unroll
        for (int o = 16; o; o >>= 1) m = fmaxf(m, __shfl_xor_sync(0xffffffffu, m, o));
        float e = act ? expf(v - m) : 0.0f;
        float sum = e;
        #pragma unroll
        for (int o = 16; o; o >>= 1) sum += __shfl_xor_sync(0xffffffffu, sum, o);
        if (act) out[(size_t)roi * C1 + t] = e / sum;
    }
}

// ---------------------------------------------------------------------------
extern "C" void kernel_launch(void* const* d_in, const int* in_sizes, int n_in,
                              void* d_out, int out_size) {
    const float* x    = (const float*)d_in[0];
    const int*   rois = (const int*)d_in[1];
    float*       out  = (float*)d_out;
    const int n_rois  = in_sizes[1] / 4;   // 2000

    dim3 gA(H, NJL);                        // 100 x 49
    build_xsum<<<gA, 128>>>(x);

    dim3 gB((ROW_S / 2 + 127) / 128, NJL);  // 9 x 49
    build_ysum<<<gB, 128>>>();

    pool_softmax<<<n_rois, 352>>>(rois, out);
}

// round 10
// speedup vs baseline: 1.6947x; 1.0643x over previous
#include <cuda_runtime.h>
#include <cuda_bf16.h>
#include <math.h>

// Fixed shapes: cls_conv_out (4, 1029, 100, 100) fp32; rois (2000,4) int32.
// Only batch 3 used. Output (2000, 21, 1, 1) fp32.
#define KK       7
#define C1       21
#define NJL      49
#define H        100
#define W        100
#define HP       101
#define ROW_S    2124                 // HP*C1=2121 padded to mult of 4 (16B-aligned rows)
#define PLANE_S  (HP * ROW_S)
#define IN_BASE  (3 * 1029 * 10000)   // batch 3 offset

// Integral image, transposed c-innermost: I[jl][y][x][c]; ~42 MB scratch.
__device__ float g_integral[(size_t)NJL * PLANE_S];

// ---------------------------------------------------------------------------
// Kernel A: per (jl, y): float4 global load -> register shuffle-scan x-cumsum
// -> scatter STS directly into the FINAL transposed row layout in smem ->
// single cp.async.bulk (8496 B) shared->global. No per-thread store loop.
// ---------------------------------------------------------------------------
__global__ void __launch_bounds__(128) build_xsum(const float* __restrict__ in) {
    const int y    = blockIdx.x + 1;   // 1..100
    const int jl   = blockIdx.y;       // 0..48
    const int t    = threadIdx.x;
    const int w    = t >> 5, lane = t & 31;

    __shared__ __align__(16) float smt[ROW_S];  // final row: smt[x*21 + c]

    // zero the x=0 column (21) and tail padding (3)
    if (t < C1) smt[t] = 0.0f;
    if (t >= 125) smt[1996 + t] = 0.0f;          // 2121..2123

    // --- load: warp w owns channels {w, w+4, ...}; lanes 0..24 hold 1 float4
    const float4* src4 = (const float4*)(in + IN_BASE
                        + (size_t)jl * (C1 * H * W) + (size_t)(y - 1) * W);
    float4 v[6];
    #pragma unroll
    for (int k = 0; k < 6; k++) {
        const int c = w + 4 * k;
        if (c < C1 && lane < 25) v[k] = src4[c * (H * W / 4) + lane];
    }

    // --- scan each owned channel, scatter-store scanned values to smt.
    // lane l's scanned value for input x=4l+i belongs at out pos x+1:
    // smt[(4l+i+1)*21 + c] = smt[84l + 21 + i*21 + c].
    float* slane = smt + 84 * lane + C1;
    #pragma unroll
    for (int k = 0; k < 6; k++) {
        const int c = w + 4 * k;
        if (c < C1) {
            float s0 = v[k].x;
            float s1 = s0 + v[k].y;
            float s2 = s1 + v[k].z;
            float s3 = s2 + v[k].w;
            float run = s3;
            #pragma unroll
            for (int d = 1; d < 32; d <<= 1) {
                float u = __shfl_up_sync(0xffffffffu, run, d);
                if (lane >= d) run += u;
            }
            const float off = run - s3;
            if (lane < 25) {
                slane[c]          = off + s0;
                slane[c + C1]     = off + s1;
                slane[c + 2 * C1] = off + s2;
                slane[c + 3 * C1] = off + s3;
            }
        }
    }
    __syncthreads();

    // --- one bulk async store of the finished row
    if (t == 0) {
        asm volatile("fence.proxy.async.shared::cta;" ::: "memory");
        unsigned sa;
        asm("{ .reg .u64 a; cvta.to.shared.u64 a, %1; cvt.u32.u64 %0, a; }"
            : "=r"(sa) : "l"(smt));
        float* gd = g_integral + ((size_t)jl * HP + y) * ROW_S;
        asm volatile(
            "cp.async.bulk.global.shared::cta.bulk_group [%0], [%1], %2;"
            :: "l"(gd), "r"(sa), "r"(ROW_S * 4) : "memory");
        asm volatile("cp.async.bulk.commit_group;" ::: "memory");
        asm volatile("cp.async.bulk.wait_group 0;" ::: "memory");
    }
}

// ---------------------------------------------------------------------------
// Kernel B: y-cumsum over float2 slots (1062/row); writes y=0 zero row then
// 100 dependent FADD2 steps, unroll 10 for load MLP.
// ---------------------------------------------------------------------------
__global__ void build_ysum() {
    const int jl    = blockIdx.y;
    const int slot2 = blockIdx.x * blockDim.x + threadIdx.x;
    if (slot2 >= ROW_S / 2) return;

    float2* p = (float2*)(g_integral + (size_t)jl * PLANE_S) + slot2;
    const int stride2 = ROW_S / 2;      // 1062

    float2 acc = make_float2(0.f, 0.f);
    p[0] = acc;                         // y = 0 row is zero
    #pragma unroll 10
    for (int y = 1; y <= H; y++) {
        float2 v = p[(size_t)y * stride2];
        acc.x += v.x; acc.y += v.y;
        p[(size_t)y * stride2] = acc;
    }
}

// ---------------------------------------------------------------------------
// Kernel C: one block per ROI. 336 active threads (16 jl-groups x 21 c);
// per-thread register pre-reduction, 21-thread final sum, warp softmax.
// ---------------------------------------------------------------------------
__global__ void pool_softmax(const int* __restrict__ rois,
                             float* __restrict__ out) {
    const int roi = blockIdx.x;
    const int t   = threadIdx.x;
    __shared__ float s_part[336];      // [jl0*21 + c]
    __shared__ float s_avg[C1];

    const int4 r = ((const int4*)rois)[roi];   // ymin, xmin, ymax, xmax
    const int ys = (r.z - r.x) / KK;
    const int xs = (r.w - r.y) / KK;

    if (t < 336) {
        const int c   = t % C1;
        const int jl0 = t / C1;   // 0..15
        float part = 0.0f;
        #pragma unroll
        for (int jl = jl0; jl < NJL; jl += 16) {
            const int j = jl / KK, l = jl - j * KK;
            const int y0 = r.x + j * ys, y1 = y0 + ys;
            const int x0 = r.y + l * xs, x1 = x0 + xs;
            const float* P = g_integral + (size_t)jl * PLANE_S;
            const float a = P[(size_t)y1 * ROW_S + x1 * C1 + c];
            const float b = P[(size_t)y0 * ROW_S + x1 * C1 + c];
            const float d = P[(size_t)y1 * ROW_S + x0 * C1 + c];
            const float e = P[(size_t)y0 * ROW_S + x0 * C1 + c];
            part += (a - b) - (d - e);
        }
        s_part[t] = part;
    }
    __syncthreads();

    if (t < C1) {
        float acc = 0.0f;
        #pragma unroll
        for (int g = 0; g < 16; g++) acc += s_part[g * C1 + t];
        s_avg[t] = acc / (49.0f * (float)(ys * xs));
    }
    __syncthreads();

    if (t < 32) {
        const bool act = t < C1;
        float v = act ? s_avg[t] : -INFINITY;
        float m = v;
        #pragma unroll
        for (int o = 16; o; o >>= 1) m = fmaxf(m, __shfl_xor_sync(0xffffffffu, m, o));
        float e = act ? expf(v - m) : 0.0f;
        float sum = e;
        #pragma unroll
        for (int o = 16; o; o >>= 1) sum += __shfl_xor_sync(0xffffffffu, sum, o);
        if (act) out[(size_t)roi * C1 + t] = e / sum;
    }
}

// ---------------------------------------------------------------------------
extern "C" void kernel_launch(void* const* d_in, const int* in_sizes, int n_in,
                              void* d_out, int out_size) {
    const float* x    = (const float*)d_in[0];
    const int*   rois = (const int*)d_in[1];
    float*       out  = (float*)d_out;
    const int n_rois  = in_sizes[1] / 4;   // 2000

    dim3 gA(H, NJL);                        // 100 x 49
    build_xsum<<<gA, 128>>>(x);

    dim3 gB((ROW_S / 2 + 127) / 128, NJL);  // 9 x 49
    build_ysum<<<gB, 128>>>();

    pool_softmax<<<n_rois, 352>>>(rois, out);
}